// round 6
// baseline (speedup 1.0000x reference)
#include <cuda_runtime.h>
#include <math.h>

#define H 128
#define W 128
#define HW (H*W)
#define NF 64
#define TT 5
#define BB 2

// ---------------- scratch ----------------
__device__ float g_feats[BB*TT*NF*HW];       // NCHW
__device__ float g_fnhwc[BB*TT*HW*NF];       // NHWC
__device__ float g_half[BB*6*27*HW];
__device__ float g_wt[9*64*64];              // [k][c][o]

// ---------------- f32x2 helpers ----------------
typedef unsigned long long ull;
__device__ __forceinline__ ull pk2(float lo, float hi) {
    ull r; asm("mov.b64 %0, {%1,%2};" : "=l"(r) : "f"(lo), "f"(hi)); return r;
}
__device__ __forceinline__ void ffma2(ull& d, ull a, ull b) {
    asm("fma.rn.f32x2 %0, %1, %2, %0;" : "+l"(d) : "l"(a), "l"(b));
}
__device__ __forceinline__ float2 upk2(ull v) {
    float2 f; asm("mov.b64 {%0,%1}, %2;" : "=f"(f.x), "=f"(f.y) : "l"(v)); return f;
}

// ---------------- W-prep: covers all 36864 elements ----------------
__global__ void wprep_kernel(const float* __restrict__ dcn_w) {
    int i = blockIdx.x * blockDim.x + threadIdx.x;
    if (i >= 9*64*64) return;
    int o = i & 63;
    int c = (i >> 6) & 63;
    int k = i >> 12;
    g_wt[i] = dcn_w[(o*64 + c)*9 + k];
}

// ---------------- kernel A: 3->64 conv3x3 + bias + PReLU -> NCHW only ----------------
__global__ void __launch_bounds__(256) init_conv_kernel(
    const float* __restrict__ x, const float* __restrict__ wgt,
    const float* __restrict__ bias, const float* __restrict__ prelu_a)
{
    __shared__ float sx[3][18][18];
    __shared__ __align__(8) float sw[27*64];
    __shared__ __align__(8) float sb[64];
    int tid = threadIdx.x;
    int n = blockIdx.y;
    int ty0 = (blockIdx.x >> 3) * 16;
    int tx0 = (blockIdx.x & 7) * 16;

    for (int idx = tid; idx < 1728; idx += 256) {
        int oc = idx & 63;
        int r = idx >> 6;
        int ic = r / 9, tap = r % 9;
        sw[idx] = wgt[(oc*3 + ic)*9 + tap];
    }
    if (tid < 64) sb[tid] = bias[tid];

    const float* xin = x + n*3*HW;
    for (int idx = tid; idx < 3*18*18; idx += 256) {
        int c = idx / 324;
        int r = (idx / 18) % 18;
        int col = idx % 18;
        int gy = ty0 + r - 1, gx = tx0 + col - 1;
        float v = 0.f;
        if (gy >= 0 && gy < H && gx >= 0 && gx < W) v = xin[c*HW + gy*W + gx];
        sx[c][r][col] = v;
    }
    __syncthreads();

    int ly = tid >> 4, lx = tid & 15;
    ull acc2[32];
    #pragma unroll
    for (int o2 = 0; o2 < 32; o2++) acc2[o2] = *(const ull*)&sb[2*o2];

    for (int ic = 0; ic < 3; ic++) {
        #pragma unroll
        for (int tap = 0; tap < 9; tap++) {
            int dy = tap / 3, dx = tap % 3;
            float v = sx[ic][ly + dy][lx + dx];
            ull v2 = pk2(v, v);
            const ull* wp = (const ull*)&sw[(ic*9 + tap)*64];
            #pragma unroll
            for (int o2 = 0; o2 < 32; o2++) ffma2(acc2[o2], v2, wp[o2]);
        }
    }
    float a = prelu_a[0];
    int pix = (ty0 + ly)*W + (tx0 + lx);
    float* dst = g_feats + (size_t)n*NF*HW + pix;
    #pragma unroll
    for (int o2 = 0; o2 < 32; o2++) {
        float2 f = upk2(acc2[o2]);
        dst[(2*o2)*HW]   = (f.x > 0.f) ? f.x : a*f.x;
        dst[(2*o2+1)*HW] = (f.y > 0.f) ? f.y : a*f.y;
    }
}

// ---------------- transpose NCHW -> NHWC ----------------
__global__ void __launch_bounds__(256) transpose_kernel()
{
    __shared__ float tile[64][65];
    int tid = threadIdx.x;
    int n = blockIdx.y;
    int px0 = blockIdx.x * 64;
    const float* src = g_feats + (size_t)n*NF*HW + px0;
    float* dst = g_fnhwc + ((size_t)n*HW + px0)*64;

    #pragma unroll
    for (int i = 0; i < 16; i++) {
        int idx = tid + i*256;
        int c = idx >> 6, xx = idx & 63;
        tile[c][xx] = src[c*HW + xx];
    }
    __syncthreads();
    #pragma unroll
    for (int i = 0; i < 16; i++) {
        int idx = tid + i*256;
        int p = idx >> 6, c = idx & 63;
        dst[p*64 + c] = tile[c][p];
    }
}

// ---------------- kernel B v3: half offset-conv 64->27, oc split across thread halves ----------------
// 256 threads: warps 0-3 -> oc 0..13, warps 4-7 -> oc 14..26(+pad27)
// tile 16x16 px, 2 px/thread (lx, lx+8); ic chunk 8
__global__ void __launch_bounds__(256, 4) half_conv_kernel(const float* __restrict__ offm_w)
{
    __shared__ float st[8][18][19];
    __shared__ __align__(8) float ws[8*9*28];
    int tid = threadIdx.x;
    int task = blockIdx.y;
    int b = task / 6, s = task % 6;
    int tsel = (s == 0) ? 0 : (s - 1);
    int icg0 = (s == 0) ? 0 : 64;
    int y0 = (blockIdx.x >> 3) * 16;
    int x0 = (blockIdx.x & 7) * 16;

    const float* src = g_feats + (size_t)((b*TT + tsel)*NF)*HW;
    int lx = tid & 7;           // px pair (lx, lx+8)
    int ly = (tid >> 3) & 15;   // row in tile
    int h  = tid >> 7;          // oc half (warp-uniform)

    ull a0[7], a1[7];
    #pragma unroll
    for (int o2 = 0; o2 < 7; o2++) { a0[o2] = 0ULL; a1[o2] = 0ULL; }

    for (int icb = 0; icb < 64; icb += 8) {
        __syncthreads();
        // input chunk tile with halo (cols 0..17, rows padded to 19)
        for (int idx = tid; idx < 8*18*18; idx += 256) {
            int c = idx / 324;
            int r = (idx / 18) % 18;
            int col = idx % 18;
            int gy = y0 + r - 1, gx = x0 + col - 1;
            float v = 0.f;
            if (gy >= 0 && gy < H && gx >= 0 && gx < W) v = src[(icb + c)*HW + gy*W + gx];
            st[c][r][col] = v;
        }
        // weights chunk transposed, padded oc 27->28
        for (int idx = tid; idx < 8*9*28; idx += 256) {
            int oc = idx % 28;
            int r = idx / 28;          // 0..71
            int tap = r % 9, c = r / 9;
            ws[idx] = (oc < 27) ? offm_w[(oc*128 + icg0 + icb + c)*9 + tap] : 0.f;
        }
        __syncthreads();

        #pragma unroll
        for (int c = 0; c < 8; c++) {
            #pragma unroll
            for (int tap = 0; tap < 9; tap++) {
                int dy = tap / 3, dx = tap % 3;
                float v0 = st[c][ly + dy][lx + dx];
                float v1 = st[c][ly + dy][lx + 8 + dx];
                ull v02 = pk2(v0, v0);
                ull v12 = pk2(v1, v1);
                const ull* wp = (const ull*)&ws[(c*9 + tap)*28] + h*7;
                #pragma unroll
                for (int o2 = 0; o2 < 7; o2++) {
                    ull w2 = wp[o2];
                    ffma2(a0[o2], v02, w2);
                    ffma2(a1[o2], v12, w2);
                }
            }
        }
    }
    float* dst = g_half + (size_t)(task*27)*HW + (y0 + ly)*W + x0;
    #pragma unroll
    for (int o2 = 0; o2 < 7; o2++) {
        float2 f0 = upk2(a0[o2]);
        float2 f1 = upk2(a1[o2]);
        int oc = h*14 + 2*o2;
        dst[oc*HW + lx] = f0.x;
        dst[oc*HW + lx + 8] = f1.x;
        if (oc + 1 < 27) {
            dst[(oc+1)*HW + lx] = f0.y;
            dst[(oc+1)*HW + lx + 8] = f1.y;
        }
    }
}

// ---------------- kernel C: dcn (R5 verbatim), 4 blocks/SM ----------------
__global__ void __launch_bounds__(128, 4) dcn_kernel(
    const float* __restrict__ offm_b, const float* __restrict__ dcn_b,
    float* __restrict__ out)
{
    extern __shared__ __align__(16) float smem[];
    float* S   = smem;                                 // [c][128], 8-px blocks xor-swizzled
    float* Wt  = smem + 64*128;                        // [c][o]
    int*   sAi = (int*)(smem + 64*128 + 64*64);        // [4][128]
    float* sWm = (float*)(sAi + 4*128);                // [4][128]

    int tid = threadIdx.x;
    int jb = blockIdx.y;
    int j = jb >> 1, b = jb & 1;
    int y = blockIdx.x;

    const float* fb = g_fnhwc + (size_t)(b*TT + j)*HW*64;
    const float* h0 = g_half + (size_t)((b*6 + 0)*27)*HW;
    const float* h1 = g_half + (size_t)((b*6 + 1 + j)*27)*HW;

    int tx = tid & 15;
    int ty = tid >> 4;

    ull acc2[8][4];
    #pragma unroll
    for (int o = 0; o < 8; o++)
        #pragma unroll
        for (int p = 0; p < 4; p++) acc2[o][p] = 0ULL;

    for (int k = 0; k < 9; k++) {
        __syncthreads();

        #pragma unroll
        for (int i = 0; i < 32; i++) Wt[tid + i*128] = g_wt[k*4096 + tid + i*128];

        {
            int gx = tid;
            int pix = y*W + gx;
            float oy = h0[k*HW + pix] + h1[k*HW + pix] + offm_b[k];
            float ox = h0[(9+k)*HW + pix] + h1[(9+k)*HW + pix] + offm_b[9+k];
            float mm = h0[(18+k)*HW + pix] + h1[(18+k)*HW + pix] + offm_b[18+k];
            float mask = 1.f / (1.f + expf(-mm));
            float py  = (float)(y + (k/3) - 1) + oy;
            float pxf = (float)(gx + (k%3) - 1) + ox;
            float y0f = floorf(py), x0f = floorf(pxf);
            float lyf = py - y0f, lxf = pxf - x0f;
            int yi = (int)y0f, xi = (int)x0f;
            bool vy0 = (yi >= 0) & (yi < H);
            bool vy1 = (yi >= -1) & (yi < H-1);
            bool vx0 = (xi >= 0) & (xi < W);
            bool vx1 = (xi >= -1) & (xi < W-1);
            int yc0 = min(max(yi, 0), H-1);
            int yc1 = min(max(yi+1, 0), H-1);
            int xc0 = min(max(xi, 0), W-1);
            int xc1 = min(max(xi+1, 0), W-1);
            float wy0 = 1.f - lyf, wy1 = lyf, wx0 = 1.f - lxf, wx1 = lxf;
            sAi[0*128 + tid] = (yc0*W + xc0) * 64;  sWm[0*128 + tid] = (vy0 && vx0) ? wy0*wx0*mask : 0.f;
            sAi[1*128 + tid] = (yc0*W + xc1) * 64;  sWm[1*128 + tid] = (vy0 && vx1) ? wy0*wx1*mask : 0.f;
            sAi[2*128 + tid] = (yc1*W + xc0) * 64;  sWm[2*128 + tid] = (vy1 && vx0) ? wy1*wx0*mask : 0.f;
            sAi[3*128 + tid] = (yc1*W + xc1) * 64;  sWm[3*128 + tid] = (vy1 && vx1) ? wy1*wx1*mask : 0.f;
        }
        __syncthreads();

        #pragma unroll
        for (int it = 0; it < 8; it++) {
            int task = tid + it*128;
            int px = task >> 3;
            int q = task & 7;
            int a0 = sAi[0*128 + px], a1 = sAi[1*128 + px];
            int a2 = sAi[2*128 + px], a3 = sAi[3*128 + px];
            float w0 = sWm[0*128 + px], w1 = sWm[1*128 + px];
            float w2 = sWm[2*128 + px], w3 = sWm[3*128 + px];
            int blk = px >> 3, pof = px & 7;
            #pragma unroll
            for (int i = 0; i < 2; i++) {
                int ch4 = q + i*8;
                float4 v0 = *(const float4*)(fb + a0 + ch4*4);
                float4 v1 = *(const float4*)(fb + a1 + ch4*4);
                float4 v2 = *(const float4*)(fb + a2 + ch4*4);
                float4 v3 = *(const float4*)(fb + a3 + ch4*4);
                float4 r;
                r.x = fmaf(w3, v3.x, fmaf(w2, v2.x, fmaf(w1, v1.x, w0*v0.x)));
                r.y = fmaf(w3, v3.y, fmaf(w2, v2.y, fmaf(w1, v1.y, w0*v0.y)));
                r.z = fmaf(w3, v3.z, fmaf(w2, v2.z, fmaf(w1, v1.z, w0*v0.z)));
                r.w = fmaf(w3, v3.w, fmaf(w2, v2.w, fmaf(w1, v1.w, w0*v0.w)));
                int xb = ((blk ^ (ch4 & 3)) << 3) + pof;
                int c0 = ch4*4;
                S[(c0+0)*128 + xb] = r.x;
                S[(c0+1)*128 + xb] = r.y;
                S[(c0+2)*128 + xb] = r.z;
                S[(c0+3)*128 + xb] = r.w;
            }
        }
        __syncthreads();

        #pragma unroll 4
        for (int kk = 0; kk < 64; kk++) {
            float4 wA0 = *(const float4*)&Wt[kk*64 + ty*8];
            float4 wA1 = *(const float4*)&Wt[kk*64 + ty*8 + 4];
            int xb = (tx ^ ((kk >> 2) & 3)) << 3;
            const ull* bp = (const ull*)&S[kk*128 + xb];
            ull b0 = bp[0], b1 = bp[1], b2 = bp[2], b3 = bp[3];
            ull sv;
            sv = pk2(wA0.x, wA0.x); ffma2(acc2[0][0], sv, b0); ffma2(acc2[0][1], sv, b1); ffma2(acc2[0][2], sv, b2); ffma2(acc2[0][3], sv, b3);
            sv = pk2(wA0.y, wA0.y); ffma2(acc2[1][0], sv, b0); ffma2(acc2[1][1], sv, b1); ffma2(acc2[1][2], sv, b2); ffma2(acc2[1][3], sv, b3);
            sv = pk2(wA0.z, wA0.z); ffma2(acc2[2][0], sv, b0); ffma2(acc2[2][1], sv, b1); ffma2(acc2[2][2], sv, b2); ffma2(acc2[2][3], sv, b3);
            sv = pk2(wA0.w, wA0.w); ffma2(acc2[3][0], sv, b0); ffma2(acc2[3][1], sv, b1); ffma2(acc2[3][2], sv, b2); ffma2(acc2[3][3], sv, b3);
            sv = pk2(wA1.x, wA1.x); ffma2(acc2[4][0], sv, b0); ffma2(acc2[4][1], sv, b1); ffma2(acc2[4][2], sv, b2); ffma2(acc2[4][3], sv, b3);
            sv = pk2(wA1.y, wA1.y); ffma2(acc2[5][0], sv, b0); ffma2(acc2[5][1], sv, b1); ffma2(acc2[5][2], sv, b2); ffma2(acc2[5][3], sv, b3);
            sv = pk2(wA1.z, wA1.z); ffma2(acc2[6][0], sv, b0); ffma2(acc2[6][1], sv, b1); ffma2(acc2[6][2], sv, b2); ffma2(acc2[6][3], sv, b3);
            sv = pk2(wA1.w, wA1.w); ffma2(acc2[7][0], sv, b0); ffma2(acc2[7][1], sv, b1); ffma2(acc2[7][2], sv, b2); ffma2(acc2[7][3], sv, b3);
        }
    }

    float* ob = out + (size_t)jb*64*HW + y*W + tx*8;
    #pragma unroll
    for (int o = 0; o < 8; o++) {
        int oc = ty*8 + o;
        float bi = __ldg(&dcn_b[oc]);
        float2 f0 = upk2(acc2[o][0]);
        float2 f1 = upk2(acc2[o][1]);
        float2 f2 = upk2(acc2[o][2]);
        float2 f3 = upk2(acc2[o][3]);
        float4 lo, hi;
        lo.x = f0.x + bi; lo.y = f0.y + bi; lo.z = f1.x + bi; lo.w = f1.y + bi;
        hi.x = f2.x + bi; hi.y = f2.y + bi; hi.z = f3.x + bi; hi.w = f3.y + bi;
        *(float4*)(ob + (size_t)oc*HW) = lo;
        *(float4*)(ob + (size_t)oc*HW + 4) = hi;
    }
}

// ---------------- launch ----------------
extern "C" void kernel_launch(void* const* d_in, const int* in_sizes, int n_in,
                              void* d_out, int out_size) {
    const float* x       = (const float*)d_in[0];
    const float* init_w  = (const float*)d_in[1];
    const float* init_b  = (const float*)d_in[2];
    const float* prelu_a = (const float*)d_in[3];
    const float* offm_w  = (const float*)d_in[4];
    const float* offm_b  = (const float*)d_in[5];
    const float* dcn_w   = (const float*)d_in[6];
    const float* dcn_b   = (const float*)d_in[7];
    float* out = (float*)d_out;

    static bool attr_set = false;
    if (!attr_set) {
        cudaFuncSetAttribute(dcn_kernel, cudaFuncAttributeMaxDynamicSharedMemorySize, 53248);
        attr_set = true;
    }

    wprep_kernel<<<(9*64*64 + 255)/256, 256>>>(dcn_w);   // 144 blocks
    init_conv_kernel<<<dim3(64, 10), 256>>>(x, init_w, init_b, prelu_a);
    transpose_kernel<<<dim3(256, 10), 256>>>();
    half_conv_kernel<<<dim3(64, 12), 256>>>(offm_w);
    dcn_kernel<<<dim3(128, 10), 128, 53248>>>(offm_b, dcn_b, out);
}

// round 7
// speedup vs baseline: 1.0191x; 1.0191x over previous
#include <cuda_runtime.h>
#include <math.h>

#define H 128
#define W 128
#define HW (H*W)
#define NF 64
#define TT 5
#define BB 2

// ---------------- scratch ----------------
__device__ float g_feats[BB*TT*NF*HW];       // NCHW
__device__ float g_fnhwc[BB*TT*HW*NF];       // NHWC
__device__ float g_half[BB*6*27*HW];
__device__ float g_wt[9*64*64];              // [k][c][o]

// ---------------- f32x2 helpers ----------------
typedef unsigned long long ull;
__device__ __forceinline__ ull pk2(float lo, float hi) {
    ull r; asm("mov.b64 %0, {%1,%2};" : "=l"(r) : "f"(lo), "f"(hi)); return r;
}
__device__ __forceinline__ void ffma2(ull& d, ull a, ull b) {
    asm("fma.rn.f32x2 %0, %1, %2, %0;" : "+l"(d) : "l"(a), "l"(b));
}
__device__ __forceinline__ float2 upk2(ull v) {
    float2 f; asm("mov.b64 {%0,%1}, %2;" : "=f"(f.x), "=f"(f.y) : "l"(v)); return f;
}

// ---------------- W-prep: covers all 36864 elements ----------------
__global__ void wprep_kernel(const float* __restrict__ dcn_w) {
    int i = blockIdx.x * blockDim.x + threadIdx.x;
    if (i >= 9*64*64) return;
    int o = i & 63;
    int c = (i >> 6) & 63;
    int k = i >> 12;
    g_wt[i] = dcn_w[(o*64 + c)*9 + k];
}

// ---------------- kernel A: 3->64 conv3x3 + bias + PReLU -> NCHW only ----------------
__global__ void __launch_bounds__(256) init_conv_kernel(
    const float* __restrict__ x, const float* __restrict__ wgt,
    const float* __restrict__ bias, const float* __restrict__ prelu_a)
{
    __shared__ float sx[3][18][18];
    __shared__ __align__(8) float sw[27*64];
    __shared__ __align__(8) float sb[64];
    int tid = threadIdx.x;
    int n = blockIdx.y;
    int ty0 = (blockIdx.x >> 3) * 16;
    int tx0 = (blockIdx.x & 7) * 16;

    for (int idx = tid; idx < 1728; idx += 256) {
        int oc = idx & 63;
        int r = idx >> 6;
        int ic = r / 9, tap = r % 9;
        sw[idx] = wgt[(oc*3 + ic)*9 + tap];
    }
    if (tid < 64) sb[tid] = bias[tid];

    const float* xin = x + n*3*HW;
    for (int idx = tid; idx < 3*18*18; idx += 256) {
        int c = idx / 324;
        int r = (idx / 18) % 18;
        int col = idx % 18;
        int gy = ty0 + r - 1, gx = tx0 + col - 1;
        float v = 0.f;
        if (gy >= 0 && gy < H && gx >= 0 && gx < W) v = xin[c*HW + gy*W + gx];
        sx[c][r][col] = v;
    }
    __syncthreads();

    int ly = tid >> 4, lx = tid & 15;
    ull acc2[32];
    #pragma unroll
    for (int o2 = 0; o2 < 32; o2++) acc2[o2] = *(const ull*)&sb[2*o2];

    for (int ic = 0; ic < 3; ic++) {
        #pragma unroll
        for (int tap = 0; tap < 9; tap++) {
            int dy = tap / 3, dx = tap % 3;
            float v = sx[ic][ly + dy][lx + dx];
            ull v2 = pk2(v, v);
            const ull* wp = (const ull*)&sw[(ic*9 + tap)*64];
            #pragma unroll
            for (int o2 = 0; o2 < 32; o2++) ffma2(acc2[o2], v2, wp[o2]);
        }
    }
    float a = prelu_a[0];
    int pix = (ty0 + ly)*W + (tx0 + lx);
    float* dst = g_feats + (size_t)n*NF*HW + pix;
    #pragma unroll
    for (int o2 = 0; o2 < 32; o2++) {
        float2 f = upk2(acc2[o2]);
        dst[(2*o2)*HW]   = (f.x > 0.f) ? f.x : a*f.x;
        dst[(2*o2+1)*HW] = (f.y > 0.f) ? f.y : a*f.y;
    }
}

// ---------------- transpose NCHW -> NHWC ----------------
__global__ void __launch_bounds__(256) transpose_kernel()
{
    __shared__ float tile[64][65];
    int tid = threadIdx.x;
    int n = blockIdx.y;
    int px0 = blockIdx.x * 64;
    const float* src = g_feats + (size_t)n*NF*HW + px0;
    float* dst = g_fnhwc + ((size_t)n*HW + px0)*64;

    #pragma unroll
    for (int i = 0; i < 16; i++) {
        int idx = tid + i*256;
        int c = idx >> 6, xx = idx & 63;
        tile[c][xx] = src[c*HW + xx];
    }
    __syncthreads();
    #pragma unroll
    for (int i = 0; i < 16; i++) {
        int idx = tid + i*256;
        int p = idx >> 6, c = idx & 63;
        dst[p*64 + c] = tile[c][p];
    }
}

// ---------------- kernel B v4: half offset-conv, 4 px/thread, oc quartered ----------------
// 256 threads: q = tid>>6 selects oc quarter (7 real oc each, padded to 8)
// tile 16x16 px; each px-thread handles 4 contiguous px via LDS.128+LDS.64 input windows
__global__ void __launch_bounds__(256, 3) half_conv_kernel(const float* __restrict__ offm_w)
{
    __shared__ float st[8][18][20];               // [c][row][col], col 0 = x0-1, pad 20
    __shared__ __align__(8) float ws[8*9*32];     // [c][tap][q*8+i], oc = q*7+i (i<7)
    int tid = threadIdx.x;
    int task = blockIdx.y;
    int b = task / 6, s = task % 6;
    int tsel = (s == 0) ? 0 : (s - 1);
    int icg0 = (s == 0) ? 0 : 64;
    int y0 = (blockIdx.x >> 3) * 16;
    int x0 = (blockIdx.x & 7) * 16;

    const float* src = g_feats + (size_t)((b*TT + tsel)*NF)*HW;
    int q  = tid >> 6;           // oc quarter (warp-uniform)
    int r  = tid & 63;
    int ly = r >> 2;             // row in tile
    int lx = r & 3;              // px group: 4 px at 4*lx

    ull acc2[4][4];              // [oc-pair][px]
    #pragma unroll
    for (int o2 = 0; o2 < 4; o2++)
        #pragma unroll
        for (int p = 0; p < 4; p++) acc2[o2][p] = 0ULL;

    for (int icb = 0; icb < 64; icb += 8) {
        __syncthreads();
        // input chunk tile with halo
        for (int idx = tid; idx < 8*18*18; idx += 256) {
            int c = idx / 324;
            int rr = (idx / 18) % 18;
            int col = idx % 18;
            int gy = y0 + rr - 1, gx = x0 + col - 1;
            float v = 0.f;
            if (gy >= 0 && gy < H && gx >= 0 && gx < W) v = src[(icb + c)*HW + gy*W + gx];
            st[c][rr][col] = v;
        }
        // weights chunk, quartered layout
        for (int idx = tid; idx < 8*9*32; idx += 256) {
            int slot = idx & 31;
            int qq = slot >> 3, ii = slot & 7;
            int oc = qq*7 + ii;
            int rr = idx >> 5;
            int tap = rr % 9, c = rr / 9;
            ws[idx] = (ii < 7 && oc < 27) ? offm_w[(oc*128 + icg0 + icb + c)*9 + tap] : 0.f;
        }
        __syncthreads();

        #pragma unroll
        for (int c = 0; c < 8; c++) {
            #pragma unroll
            for (int dy = 0; dy < 3; dy++) {
                const float* rp = &st[c][ly + dy][4*lx];
                float4 i4 = *(const float4*)rp;
                float2 i2 = *(const float2*)(rp + 4);
                ull iv[6];
                iv[0] = pk2(i4.x, i4.x); iv[1] = pk2(i4.y, i4.y); iv[2] = pk2(i4.z, i4.z);
                iv[3] = pk2(i4.w, i4.w); iv[4] = pk2(i2.x, i2.x); iv[5] = pk2(i2.y, i2.y);
                #pragma unroll
                for (int dx = 0; dx < 3; dx++) {
                    const ull* wp = (const ull*)&ws[(c*9 + dy*3 + dx)*32 + q*8];
                    ull w0 = wp[0], w1 = wp[1], w2 = wp[2], w3 = wp[3];
                    #pragma unroll
                    for (int p = 0; p < 4; p++) {
                        ull v = iv[p + dx];
                        ffma2(acc2[0][p], v, w0);
                        ffma2(acc2[1][p], v, w1);
                        ffma2(acc2[2][p], v, w2);
                        ffma2(acc2[3][p], v, w3);
                    }
                }
            }
        }
    }
    // write: one float4 per real oc
    float* dst = g_half + (size_t)(task*27)*HW + (y0 + ly)*W + x0 + 4*lx;
    #pragma unroll
    for (int i = 0; i < 7; i++) {
        int oc = q*7 + i;
        if (oc >= 27) break;
        float4 v;
        float* vv = (float*)&v;
        #pragma unroll
        for (int p = 0; p < 4; p++) {
            float2 f = upk2(acc2[i >> 1][p]);
            vv[p] = (i & 1) ? f.y : f.x;
        }
        *(float4*)(dst + (size_t)oc*HW) = v;
    }
}

// ---------------- kernel C: dcn (unchanged), 4 blocks/SM ----------------
__global__ void __launch_bounds__(128, 4) dcn_kernel(
    const float* __restrict__ offm_b, const float* __restrict__ dcn_b,
    float* __restrict__ out)
{
    extern __shared__ __align__(16) float smem[];
    float* S   = smem;                                 // [c][128], 8-px blocks xor-swizzled
    float* Wt  = smem + 64*128;                        // [c][o]
    int*   sAi = (int*)(smem + 64*128 + 64*64);        // [4][128]
    float* sWm = (float*)(sAi + 4*128);                // [4][128]

    int tid = threadIdx.x;
    int jb = blockIdx.y;
    int j = jb >> 1, b = jb & 1;
    int y = blockIdx.x;

    const float* fb = g_fnhwc + (size_t)(b*TT + j)*HW*64;
    const float* h0 = g_half + (size_t)((b*6 + 0)*27)*HW;
    const float* h1 = g_half + (size_t)((b*6 + 1 + j)*27)*HW;

    int tx = tid & 15;
    int ty = tid >> 4;

    ull acc2[8][4];
    #pragma unroll
    for (int o = 0; o < 8; o++)
        #pragma unroll
        for (int p = 0; p < 4; p++) acc2[o][p] = 0ULL;

    for (int k = 0; k < 9; k++) {
        __syncthreads();

        #pragma unroll
        for (int i = 0; i < 32; i++) Wt[tid + i*128] = g_wt[k*4096 + tid + i*128];

        {
            int gx = tid;
            int pix = y*W + gx;
            float oy = h0[k*HW + pix] + h1[k*HW + pix] + offm_b[k];
            float ox = h0[(9+k)*HW + pix] + h1[(9+k)*HW + pix] + offm_b[9+k];
            float mm = h0[(18+k)*HW + pix] + h1[(18+k)*HW + pix] + offm_b[18+k];
            float mask = 1.f / (1.f + expf(-mm));
            float py  = (float)(y + (k/3) - 1) + oy;
            float pxf = (float)(gx + (k%3) - 1) + ox;
            float y0f = floorf(py), x0f = floorf(pxf);
            float lyf = py - y0f, lxf = pxf - x0f;
            int yi = (int)y0f, xi = (int)x0f;
            bool vy0 = (yi >= 0) & (yi < H);
            bool vy1 = (yi >= -1) & (yi < H-1);
            bool vx0 = (xi >= 0) & (xi < W);
            bool vx1 = (xi >= -1) & (xi < W-1);
            int yc0 = min(max(yi, 0), H-1);
            int yc1 = min(max(yi+1, 0), H-1);
            int xc0 = min(max(xi, 0), W-1);
            int xc1 = min(max(xi+1, 0), W-1);
            float wy0 = 1.f - lyf, wy1 = lyf, wx0 = 1.f - lxf, wx1 = lxf;
            sAi[0*128 + tid] = (yc0*W + xc0) * 64;  sWm[0*128 + tid] = (vy0 && vx0) ? wy0*wx0*mask : 0.f;
            sAi[1*128 + tid] = (yc0*W + xc1) * 64;  sWm[1*128 + tid] = (vy0 && vx1) ? wy0*wx1*mask : 0.f;
            sAi[2*128 + tid] = (yc1*W + xc0) * 64;  sWm[2*128 + tid] = (vy1 && vx0) ? wy1*wx0*mask : 0.f;
            sAi[3*128 + tid] = (yc1*W + xc1) * 64;  sWm[3*128 + tid] = (vy1 && vx1) ? wy1*wx1*mask : 0.f;
        }
        __syncthreads();

        #pragma unroll
        for (int it = 0; it < 8; it++) {
            int task = tid + it*128;
            int px = task >> 3;
            int q = task & 7;
            int a0 = sAi[0*128 + px], a1 = sAi[1*128 + px];
            int a2 = sAi[2*128 + px], a3 = sAi[3*128 + px];
            float w0 = sWm[0*128 + px], w1 = sWm[1*128 + px];
            float w2 = sWm[2*128 + px], w3 = sWm[3*128 + px];
            int blk = px >> 3, pof = px & 7;
            #pragma unroll
            for (int i = 0; i < 2; i++) {
                int ch4 = q + i*8;
                float4 v0 = *(const float4*)(fb + a0 + ch4*4);
                float4 v1 = *(const float4*)(fb + a1 + ch4*4);
                float4 v2 = *(const float4*)(fb + a2 + ch4*4);
                float4 v3 = *(const float4*)(fb + a3 + ch4*4);
                float4 r;
                r.x = fmaf(w3, v3.x, fmaf(w2, v2.x, fmaf(w1, v1.x, w0*v0.x)));
                r.y = fmaf(w3, v3.y, fmaf(w2, v2.y, fmaf(w1, v1.y, w0*v0.y)));
                r.z = fmaf(w3, v3.z, fmaf(w2, v2.z, fmaf(w1, v1.z, w0*v0.z)));
                r.w = fmaf(w3, v3.w, fmaf(w2, v2.w, fmaf(w1, v1.w, w0*v0.w)));
                int xb = ((blk ^ (ch4 & 3)) << 3) + pof;
                int c0 = ch4*4;
                S[(c0+0)*128 + xb] = r.x;
                S[(c0+1)*128 + xb] = r.y;
                S[(c0+2)*128 + xb] = r.z;
                S[(c0+3)*128 + xb] = r.w;
            }
        }
        __syncthreads();

        #pragma unroll 4
        for (int kk = 0; kk < 64; kk++) {
            float4 wA0 = *(const float4*)&Wt[kk*64 + ty*8];
            float4 wA1 = *(const float4*)&Wt[kk*64 + ty*8 + 4];
            int xb = (tx ^ ((kk >> 2) & 3)) << 3;
            const ull* bp = (const ull*)&S[kk*128 + xb];
            ull b0 = bp[0], b1 = bp[1], b2 = bp[2], b3 = bp[3];
            ull sv;
            sv = pk2(wA0.x, wA0.x); ffma2(acc2[0][0], sv, b0); ffma2(acc2[0][1], sv, b1); ffma2(acc2[0][2], sv, b2); ffma2(acc2[0][3], sv, b3);
            sv = pk2(wA0.y, wA0.y); ffma2(acc2[1][0], sv, b0); ffma2(acc2[1][1], sv, b1); ffma2(acc2[1][2], sv, b2); ffma2(acc2[1][3], sv, b3);
            sv = pk2(wA0.z, wA0.z); ffma2(acc2[2][0], sv, b0); ffma2(acc2[2][1], sv, b1); ffma2(acc2[2][2], sv, b2); ffma2(acc2[2][3], sv, b3);
            sv = pk2(wA0.w, wA0.w); ffma2(acc2[3][0], sv, b0); ffma2(acc2[3][1], sv, b1); ffma2(acc2[3][2], sv, b2); ffma2(acc2[3][3], sv, b3);
            sv = pk2(wA1.x, wA1.x); ffma2(acc2[4][0], sv, b0); ffma2(acc2[4][1], sv, b1); ffma2(acc2[4][2], sv, b2); ffma2(acc2[4][3], sv, b3);
            sv = pk2(wA1.y, wA1.y); ffma2(acc2[5][0], sv, b0); ffma2(acc2[5][1], sv, b1); ffma2(acc2[5][2], sv, b2); ffma2(acc2[5][3], sv, b3);
            sv = pk2(wA1.z, wA1.z); ffma2(acc2[6][0], sv, b0); ffma2(acc2[6][1], sv, b1); ffma2(acc2[6][2], sv, b2); ffma2(acc2[6][3], sv, b3);
            sv = pk2(wA1.w, wA1.w); ffma2(acc2[7][0], sv, b0); ffma2(acc2[7][1], sv, b1); ffma2(acc2[7][2], sv, b2); ffma2(acc2[7][3], sv, b3);
        }
    }

    float* ob = out + (size_t)jb*64*HW + y*W + tx*8;
    #pragma unroll
    for (int o = 0; o < 8; o++) {
        int oc = ty*8 + o;
        float bi = __ldg(&dcn_b[oc]);
        float2 f0 = upk2(acc2[o][0]);
        float2 f1 = upk2(acc2[o][1]);
        float2 f2 = upk2(acc2[o][2]);
        float2 f3 = upk2(acc2[o][3]);
        float4 lo, hi;
        lo.x = f0.x + bi; lo.y = f0.y + bi; lo.z = f1.x + bi; lo.w = f1.y + bi;
        hi.x = f2.x + bi; hi.y = f2.y + bi; hi.z = f3.x + bi; hi.w = f3.y + bi;
        *(float4*)(ob + (size_t)oc*HW) = lo;
        *(float4*)(ob + (size_t)oc*HW + 4) = hi;
    }
}

// ---------------- launch ----------------
extern "C" void kernel_launch(void* const* d_in, const int* in_sizes, int n_in,
                              void* d_out, int out_size) {
    const float* x       = (const float*)d_in[0];
    const float* init_w  = (const float*)d_in[1];
    const float* init_b  = (const float*)d_in[2];
    const float* prelu_a = (const float*)d_in[3];
    const float* offm_w  = (const float*)d_in[4];
    const float* offm_b  = (const float*)d_in[5];
    const float* dcn_w   = (const float*)d_in[6];
    const float* dcn_b   = (const float*)d_in[7];
    float* out = (float*)d_out;

    static bool attr_set = false;
    if (!attr_set) {
        cudaFuncSetAttribute(dcn_kernel, cudaFuncAttributeMaxDynamicSharedMemorySize, 53248);
        attr_set = true;
    }

    wprep_kernel<<<(9*64*64 + 255)/256, 256>>>(dcn_w);   // 144 blocks
    init_conv_kernel<<<dim3(64, 10), 256>>>(x, init_w, init_b, prelu_a);
    transpose_kernel<<<dim3(256, 10), 256>>>();
    half_conv_kernel<<<dim3(64, 12), 256>>>(offm_w);
    dcn_kernel<<<dim3(128, 10), 128, 53248>>>(offm_b, dcn_b, out);
}

// round 9
// speedup vs baseline: 1.0301x; 1.0108x over previous
#include <cuda_runtime.h>
#include <stdint.h>
#include <math.h>

#define H 128
#define W 128
#define HW (H*W)
#define NF 64
#define TT 5
#define BB 2

// ---------------- scratch ----------------
__device__ float g_feats[BB*TT*NF*HW];       // NCHW
__device__ float g_fnhwc[BB*TT*HW*NF];       // NHWC
__device__ float g_half[BB*6*27*HW];
__device__ float g_wt[9*64*64];              // [k][c][o]

// ---------------- f32x2 helpers ----------------
typedef unsigned long long ull;
__device__ __forceinline__ ull pk2(float lo, float hi) {
    ull r; asm("mov.b64 %0, {%1,%2};" : "=l"(r) : "f"(lo), "f"(hi)); return r;
}
__device__ __forceinline__ void ffma2(ull& d, ull a, ull b) {
    asm("fma.rn.f32x2 %0, %1, %2, %0;" : "+l"(d) : "l"(a), "l"(b));
}
__device__ __forceinline__ float2 upk2(ull v) {
    float2 f; asm("mov.b64 {%0,%1}, %2;" : "=f"(f.x), "=f"(f.y) : "l"(v)); return f;
}
// cp.async 4B with zero-fill predicate (src-size 0 -> dst zero-filled)
__device__ __forceinline__ void cp_async4(uint32_t saddr, const float* g, bool pred) {
    int bytes = pred ? 4 : 0;
    asm volatile("cp.async.ca.shared.global [%0], [%1], 4, %2;" :: "r"(saddr), "l"(g), "r"(bytes));
}

// ---------------- W-prep: covers all 36864 elements ----------------
__global__ void wprep_kernel(const float* __restrict__ dcn_w) {
    int i = blockIdx.x * blockDim.x + threadIdx.x;
    if (i >= 9*64*64) return;
    int o = i & 63;
    int c = (i >> 6) & 63;
    int k = i >> 12;
    g_wt[i] = dcn_w[(o*64 + c)*9 + k];
}

// ---------------- kernel A: 3->64 conv3x3 + bias + PReLU -> NCHW only ----------------
__global__ void __launch_bounds__(256) init_conv_kernel(
    const float* __restrict__ x, const float* __restrict__ wgt,
    const float* __restrict__ bias, const float* __restrict__ prelu_a)
{
    __shared__ float sx[3][18][18];
    __shared__ __align__(8) float sw[27*64];
    __shared__ __align__(8) float sb[64];
    int tid = threadIdx.x;
    int n = blockIdx.y;
    int ty0 = (blockIdx.x >> 3) * 16;
    int tx0 = (blockIdx.x & 7) * 16;

    for (int idx = tid; idx < 1728; idx += 256) {
        int oc = idx & 63;
        int r = idx >> 6;
        int ic = r / 9, tap = r % 9;
        sw[idx] = wgt[(oc*3 + ic)*9 + tap];
    }
    if (tid < 64) sb[tid] = bias[tid];

    const float* xin = x + n*3*HW;
    for (int idx = tid; idx < 3*18*18; idx += 256) {
        int c = idx / 324;
        int r = (idx / 18) % 18;
        int col = idx % 18;
        int gy = ty0 + r - 1, gx = tx0 + col - 1;
        float v = 0.f;
        if (gy >= 0 && gy < H && gx >= 0 && gx < W) v = xin[c*HW + gy*W + gx];
        sx[c][r][col] = v;
    }
    __syncthreads();

    int ly = tid >> 4, lx = tid & 15;
    ull acc2[32];
    #pragma unroll
    for (int o2 = 0; o2 < 32; o2++) acc2[o2] = *(const ull*)&sb[2*o2];

    for (int ic = 0; ic < 3; ic++) {
        #pragma unroll
        for (int tap = 0; tap < 9; tap++) {
            int dy = tap / 3, dx = tap % 3;
            float v = sx[ic][ly + dy][lx + dx];
            ull v2 = pk2(v, v);
            const ull* wp = (const ull*)&sw[(ic*9 + tap)*64];
            #pragma unroll
            for (int o2 = 0; o2 < 32; o2++) ffma2(acc2[o2], v2, wp[o2]);
        }
    }
    float a = prelu_a[0];
    int pix = (ty0 + ly)*W + (tx0 + lx);
    float* dst = g_feats + (size_t)n*NF*HW + pix;
    #pragma unroll
    for (int o2 = 0; o2 < 32; o2++) {
        float2 f = upk2(acc2[o2]);
        dst[(2*o2)*HW]   = (f.x > 0.f) ? f.x : a*f.x;
        dst[(2*o2+1)*HW] = (f.y > 0.f) ? f.y : a*f.y;
    }
}

// ---------------- transpose NCHW -> NHWC ----------------
__global__ void __launch_bounds__(256) transpose_kernel()
{
    __shared__ float tile[64][65];
    int tid = threadIdx.x;
    int n = blockIdx.y;
    int px0 = blockIdx.x * 64;
    const float* src = g_feats + (size_t)n*NF*HW + px0;
    float* dst = g_fnhwc + ((size_t)n*HW + px0)*64;

    #pragma unroll
    for (int i = 0; i < 16; i++) {
        int idx = tid + i*256;
        int c = idx >> 6, xx = idx & 63;
        tile[c][xx] = src[c*HW + xx];
    }
    __syncthreads();
    #pragma unroll
    for (int i = 0; i < 16; i++) {
        int idx = tid + i*256;
        int p = idx >> 6, c = idx & 63;
        dst[p*64 + c] = tile[c][p];
    }
}

// ---------------- kernel B v5: half offset-conv, cp.async double-buffered pipeline ----------------
// 256 threads: q = tid>>6 selects oc quarter (7 real oc, pad 8); 4 px/thread
__global__ void __launch_bounds__(256, 3) half_conv_kernel(const float* __restrict__ offm_w)
{
    __shared__ __align__(16) float st[2][8][18][20];      // [buf][c][row][col]
    __shared__ __align__(16) float ws[2][8*9*32];         // [buf][(c*9+tap)*32 + q*8+i]
    int tid = threadIdx.x;
    int task = blockIdx.y;
    int b = task / 6, s = task % 6;
    int tsel = (s == 0) ? 0 : (s - 1);
    int icg0 = (s == 0) ? 0 : 64;
    int y0 = (blockIdx.x >> 3) * 16;
    int x0 = (blockIdx.x & 7) * 16;

    const float* src = g_feats + (size_t)((b*TT + tsel)*NF)*HW;
    int q  = tid >> 6;
    int r  = tid & 63;
    int ly = r >> 2;
    int lx = r & 3;

    uint32_t st_sm = (uint32_t)__cvta_generic_to_shared(&st[0][0][0][0]);
    uint32_t ws_sm = (uint32_t)__cvta_generic_to_shared(&ws[0][0]);
    const uint32_t ST_BUF = 8*18*20*4;
    const uint32_t WS_BUF = 8*9*32*4;

    auto stage = [&](int icb, int buf) {
        uint32_t stb = st_sm + buf*ST_BUF;
        for (int idx = tid; idx < 8*18*18; idx += 256) {
            int c = idx / 324;
            int rr = (idx / 18) % 18;
            int col = idx % 18;
            int gy = y0 + rr - 1, gx = x0 + col - 1;
            bool p = (gy >= 0) && (gy < H) && (gx >= 0) && (gx < W);
            const float* g = src + (icb + c)*HW + (p ? gy*W + gx : 0);
            cp_async4(stb + ((c*18 + rr)*20 + col)*4, g, p);
        }
        uint32_t wsb = ws_sm + buf*WS_BUF;
        for (int idx = tid; idx < 8*9*32; idx += 256) {
            int slot = idx & 31;
            int qq = slot >> 3, ii = slot & 7;
            int oc = qq*7 + ii;
            int rr = idx >> 5;
            int tap = rr % 9, c = rr / 9;
            bool p = (ii < 7) && (oc < 27);
            const float* g = offm_w + ((p ? oc : 0)*128 + icg0 + icb + c)*9 + tap;
            cp_async4(wsb + idx*4, g, p);
        }
    };

    ull acc2[4][4];
    #pragma unroll
    for (int o2 = 0; o2 < 4; o2++)
        #pragma unroll
        for (int p = 0; p < 4; p++) acc2[o2][p] = 0ULL;

    // prologue: stage chunk 0
    stage(0, 0);
    asm volatile("cp.async.commit_group;");

    for (int ci = 0; ci < 8; ci++) {
        int buf = ci & 1;
        if (ci < 7) {
            stage((ci + 1)*8, buf ^ 1);
            asm volatile("cp.async.commit_group;");
            asm volatile("cp.async.wait_group 1;");
        } else {
            asm volatile("cp.async.wait_group 0;");
        }
        __syncthreads();

        const float (*stb)[18][20] = st[buf];
        const float* wsb = ws[buf];

        #pragma unroll
        for (int c = 0; c < 8; c++) {
            #pragma unroll
            for (int dy = 0; dy < 3; dy++) {
                const float* rp = &stb[c][ly + dy][4*lx];
                float4 i4 = *(const float4*)rp;
                float2 i2 = *(const float2*)(rp + 4);
                ull iv[6];
                iv[0] = pk2(i4.x, i4.x); iv[1] = pk2(i4.y, i4.y); iv[2] = pk2(i4.z, i4.z);
                iv[3] = pk2(i4.w, i4.w); iv[4] = pk2(i2.x, i2.x); iv[5] = pk2(i2.y, i2.y);
                #pragma unroll
                for (int dx = 0; dx < 3; dx++) {
                    const ull* wp = (const ull*)&wsb[(c*9 + dy*3 + dx)*32 + q*8];
                    ull w0 = wp[0], w1 = wp[1], w2 = wp[2], w3 = wp[3];
                    #pragma unroll
                    for (int p = 0; p < 4; p++) {
                        ull v = iv[p + dx];
                        ffma2(acc2[0][p], v, w0);
                        ffma2(acc2[1][p], v, w1);
                        ffma2(acc2[2][p], v, w2);
                        ffma2(acc2[3][p], v, w3);
                    }
                }
            }
        }
        __syncthreads();   // release buf for the stage at ci+2
    }

    // write: one float4 per real oc
    float* dst = g_half + (size_t)(task*27)*HW + (y0 + ly)*W + x0 + 4*lx;
    #pragma unroll
    for (int i = 0; i < 7; i++) {
        int oc = q*7 + i;
        if (oc >= 27) break;
        float4 v;
        float* vv = (float*)&v;
        #pragma unroll
        for (int p = 0; p < 4; p++) {
            float2 f = upk2(acc2[i >> 1][p]);
            vv[p] = (i & 1) ? f.y : f.x;
        }
        *(float4*)(dst + (size_t)oc*HW) = v;
    }
}

// ---------------- kernel C: dcn (unchanged), 4 blocks/SM ----------------
__global__ void __launch_bounds__(128, 4) dcn_kernel(
    const float* __restrict__ offm_b, const float* __restrict__ dcn_b,
    float* __restrict__ out)
{
    extern __shared__ __align__(16) float smem[];
    float* S   = smem;                                 // [c][128], 8-px blocks xor-swizzled
    float* Wt  = smem + 64*128;                        // [c][o]
    int*   sAi = (int*)(smem + 64*128 + 64*64);        // [4][128]
    float* sWm = (float*)(sAi + 4*128);                // [4][128]

    int tid = threadIdx.x;
    int jb = blockIdx.y;
    int j = jb >> 1, b = jb & 1;
    int y = blockIdx.x;

    const float* fb = g_fnhwc + (size_t)(b*TT + j)*HW*64;
    const float* h0 = g_half + (size_t)((b*6 + 0)*27)*HW;
    const float* h1 = g_half + (size_t)((b*6 + 1 + j)*27)*HW;

    int tx = tid & 15;
    int ty = tid >> 4;

    ull acc2[8][4];
    #pragma unroll
    for (int o = 0; o < 8; o++)
        #pragma unroll
        for (int p = 0; p < 4; p++) acc2[o][p] = 0ULL;

    for (int k = 0; k < 9; k++) {
        __syncthreads();

        #pragma unroll
        for (int i = 0; i < 32; i++) Wt[tid + i*128] = g_wt[k*4096 + tid + i*128];

        {
            int gx = tid;
            int pix = y*W + gx;
            float oy = h0[k*HW + pix] + h1[k*HW + pix] + offm_b[k];
            float ox = h0[(9+k)*HW + pix] + h1[(9+k)*HW + pix] + offm_b[9+k];
            float mm = h0[(18+k)*HW + pix] + h1[(18+k)*HW + pix] + offm_b[18+k];
            float mask = 1.f / (1.f + expf(-mm));
            float py  = (float)(y + (k/3) - 1) + oy;
            float pxf = (float)(gx + (k%3) - 1) + ox;
            float y0f = floorf(py), x0f = floorf(pxf);
            float lyf = py - y0f, lxf = pxf - x0f;
            int yi = (int)y0f, xi = (int)x0f;
            bool vy0 = (yi >= 0) & (yi < H);
            bool vy1 = (yi >= -1) & (yi < H-1);
            bool vx0 = (xi >= 0) & (xi < W);
            bool vx1 = (xi >= -1) & (xi < W-1);
            int yc0 = min(max(yi, 0), H-1);
            int yc1 = min(max(yi+1, 0), H-1);
            int xc0 = min(max(xi, 0), W-1);
            int xc1 = min(max(xi+1, 0), W-1);
            float wy0 = 1.f - lyf, wy1 = lyf, wx0 = 1.f - lxf, wx1 = lxf;
            sAi[0*128 + tid] = (yc0*W + xc0) * 64;  sWm[0*128 + tid] = (vy0 && vx0) ? wy0*wx0*mask : 0.f;
            sAi[1*128 + tid] = (yc0*W + xc1) * 64;  sWm[1*128 + tid] = (vy0 && vx1) ? wy0*wx1*mask : 0.f;
            sAi[2*128 + tid] = (yc1*W + xc0) * 64;  sWm[2*128 + tid] = (vy1 && vx0) ? wy1*wx0*mask : 0.f;
            sAi[3*128 + tid] = (yc1*W + xc1) * 64;  sWm[3*128 + tid] = (vy1 && vx1) ? wy1*wx1*mask : 0.f;
        }
        __syncthreads();

        #pragma unroll
        for (int it = 0; it < 8; it++) {
            int task = tid + it*128;
            int px = task >> 3;
            int q = task & 7;
            int a0 = sAi[0*128 + px], a1 = sAi[1*128 + px];
            int a2 = sAi[2*128 + px], a3 = sAi[3*128 + px];
            float w0 = sWm[0*128 + px], w1 = sWm[1*128 + px];
            float w2 = sWm[2*128 + px], w3 = sWm[3*128 + px];
            int blk = px >> 3, pof = px & 7;
            #pragma unroll
            for (int i = 0; i < 2; i++) {
                int ch4 = q + i*8;
                float4 v0 = *(const float4*)(fb + a0 + ch4*4);
                float4 v1 = *(const float4*)(fb + a1 + ch4*4);
                float4 v2 = *(const float4*)(fb + a2 + ch4*4);
                float4 v3 = *(const float4*)(fb + a3 + ch4*4);
                float4 r;
                r.x = fmaf(w3, v3.x, fmaf(w2, v2.x, fmaf(w1, v1.x, w0*v0.x)));
                r.y = fmaf(w3, v3.y, fmaf(w2, v2.y, fmaf(w1, v1.y, w0*v0.y)));
                r.z = fmaf(w3, v3.z, fmaf(w2, v2.z, fmaf(w1, v1.z, w0*v0.z)));
                r.w = fmaf(w3, v3.w, fmaf(w2, v2.w, fmaf(w1, v1.w, w0*v0.w)));
                int xb = ((blk ^ (ch4 & 3)) << 3) + pof;
                int c0 = ch4*4;
                S[(c0+0)*128 + xb] = r.x;
                S[(c0+1)*128 + xb] = r.y;
                S[(c0+2)*128 + xb] = r.z;
                S[(c0+3)*128 + xb] = r.w;
            }
        }
        __syncthreads();

        #pragma unroll 4
        for (int kk = 0; kk < 64; kk++) {
            float4 wA0 = *(const float4*)&Wt[kk*64 + ty*8];
            float4 wA1 = *(const float4*)&Wt[kk*64 + ty*8 + 4];
            int xb = (tx ^ ((kk >> 2) & 3)) << 3;
            const ull* bp = (const ull*)&S[kk*128 + xb];
            ull b0 = bp[0], b1 = bp[1], b2 = bp[2], b3 = bp[3];
            ull sv;
            sv = pk2(wA0.x, wA0.x); ffma2(acc2[0][0], sv, b0); ffma2(acc2[0][1], sv, b1); ffma2(acc2[0][2], sv, b2); ffma2(acc2[0][3], sv, b3);
            sv = pk2(wA0.y, wA0.y); ffma2(acc2[1][0], sv, b0); ffma2(acc2[1][1], sv, b1); ffma2(acc2[1][2], sv, b2); ffma2(acc2[1][3], sv, b3);
            sv = pk2(wA0.z, wA0.z); ffma2(acc2[2][0], sv, b0); ffma2(acc2[2][1], sv, b1); ffma2(acc2[2][2], sv, b2); ffma2(acc2[2][3], sv, b3);
            sv = pk2(wA0.w, wA0.w); ffma2(acc2[3][0], sv, b0); ffma2(acc2[3][1], sv, b1); ffma2(acc2[3][2], sv, b2); ffma2(acc2[3][3], sv, b3);
            sv = pk2(wA1.x, wA1.x); ffma2(acc2[4][0], sv, b0); ffma2(acc2[4][1], sv, b1); ffma2(acc2[4][2], sv, b2); ffma2(acc2[4][3], sv, b3);
            sv = pk2(wA1.y, wA1.y); ffma2(acc2[5][0], sv, b0); ffma2(acc2[5][1], sv, b1); ffma2(acc2[5][2], sv, b2); ffma2(acc2[5][3], sv, b3);
            sv = pk2(wA1.z, wA1.z); ffma2(acc2[6][0], sv, b0); ffma2(acc2[6][1], sv, b1); ffma2(acc2[6][2], sv, b2); ffma2(acc2[6][3], sv, b3);
            sv = pk2(wA1.w, wA1.w); ffma2(acc2[7][0], sv, b0); ffma2(acc2[7][1], sv, b1); ffma2(acc2[7][2], sv, b2); ffma2(acc2[7][3], sv, b3);
        }
    }

    float* ob = out + (size_t)jb*64*HW + y*W + tx*8;
    #pragma unroll
    for (int o = 0; o < 8; o++) {
        int oc = ty*8 + o;
        float bi = __ldg(&dcn_b[oc]);
        float2 f0 = upk2(acc2[o][0]);
        float2 f1 = upk2(acc2[o][1]);
        float2 f2 = upk2(acc2[o][2]);
        float2 f3 = upk2(acc2[o][3]);
        float4 lo, hi;
        lo.x = f0.x + bi; lo.y = f0.y + bi; lo.z = f1.x + bi; lo.w = f1.y + bi;
        hi.x = f2.x + bi; hi.y = f2.y + bi; hi.z = f3.x + bi; hi.w = f3.y + bi;
        *(float4*)(ob + (size_t)oc*HW) = lo;
        *(float4*)(ob + (size_t)oc*HW + 4) = hi;
    }
}

// ---------------- launch ----------------
extern "C" void kernel_launch(void* const* d_in, const int* in_sizes, int n_in,
                              void* d_out, int out_size) {
    const float* x       = (const float*)d_in[0];
    const float* init_w  = (const float*)d_in[1];
    const float* init_b  = (const float*)d_in[2];
    const float* prelu_a = (const float*)d_in[3];
    const float* offm_w  = (const float*)d_in[4];
    const float* offm_b  = (const float*)d_in[5];
    const float* dcn_w   = (const float*)d_in[6];
    const float* dcn_b   = (const float*)d_in[7];
    float* out = (float*)d_out;

    static bool attr_set = false;
    if (!attr_set) {
        cudaFuncSetAttribute(dcn_kernel, cudaFuncAttributeMaxDynamicSharedMemorySize, 53248);
        attr_set = true;
    }

    wprep_kernel<<<(9*64*64 + 255)/256, 256>>>(dcn_w);   // 144 blocks
    init_conv_kernel<<<dim3(64, 10), 256>>>(x, init_w, init_b, prelu_a);
    transpose_kernel<<<dim3(256, 10), 256>>>();
    half_conv_kernel<<<dim3(64, 12), 256>>>(offm_w);
    dcn_kernel<<<dim3(128, 10), 128, 53248>>>(offm_b, dcn_b, out);
}

// round 10
// speedup vs baseline: 1.1450x; 1.1115x over previous
#include <cuda_runtime.h>
#include <stdint.h>
#include <math.h>

#define H 128
#define W 128
#define HW (H*W)
#define NF 64
#define TT 5
#define BB 2

// ---------------- scratch ----------------
__device__ float g_feats[BB*TT*NF*HW];       // NCHW
__device__ float g_fnhwc[BB*TT*HW*NF];       // NHWC
__device__ float g_half[BB*6*27*HW];
__device__ float g_wt[9*64*64];              // dcn weights [k][c][o]
__device__ float g_hw[2*64*9*32];            // half-conv weights [icg][c][tap][slot], slot=q*8+i, oc=q*7+i

// ---------------- f32x2 helpers ----------------
typedef unsigned long long ull;
__device__ __forceinline__ ull pk2(float lo, float hi) {
    ull r; asm("mov.b64 %0, {%1,%2};" : "=l"(r) : "f"(lo), "f"(hi)); return r;
}
__device__ __forceinline__ void ffma2(ull& d, ull a, ull b) {
    asm("fma.rn.f32x2 %0, %1, %2, %0;" : "+l"(d) : "l"(a), "l"(b));
}
__device__ __forceinline__ float2 upk2(ull v) {
    float2 f; asm("mov.b64 {%0,%1}, %2;" : "=f"(f.x), "=f"(f.y) : "l"(v)); return f;
}
__device__ __forceinline__ void cp_async4(uint32_t saddr, const float* g, bool pred) {
    int bytes = pred ? 4 : 0;
    asm volatile("cp.async.ca.shared.global [%0], [%1], 4, %2;" :: "r"(saddr), "l"(g), "r"(bytes));
}
__device__ __forceinline__ void cp_async16(uint32_t saddr, const float* g, bool pred) {
    int bytes = pred ? 16 : 0;
    asm volatile("cp.async.ca.shared.global [%0], [%1], 16, %2;" :: "r"(saddr), "l"(g), "r"(bytes));
}

// ---------------- W-prep: dcn weights (all 36864) ----------------
__global__ void wprep_kernel(const float* __restrict__ dcn_w) {
    int i = blockIdx.x * blockDim.x + threadIdx.x;
    if (i >= 9*64*64) return;
    int o = i & 63;
    int c = (i >> 6) & 63;
    int k = i >> 12;
    g_wt[i] = dcn_w[(o*64 + c)*9 + k];
}

// ---------------- W-prep: half-conv weights into staged layout ----------------
__global__ void whprep_kernel(const float* __restrict__ offm_w) {
    int i = blockIdx.x * blockDim.x + threadIdx.x;
    if (i >= 2*64*9*32) return;
    int slot = i & 31;
    int rest = i >> 5;             // (icg*64 + c)*9 + tap
    int tap = rest % 9;
    int cc  = rest / 9;            // icg*64 + c, 0..127
    int qq = slot >> 3, ii = slot & 7;
    int oc = qq*7 + ii;
    float v = 0.f;
    if (ii < 7 && oc < 27) v = offm_w[(oc*128 + cc)*9 + tap];
    g_hw[i] = v;
}

// ---------------- kernel A: 3->64 conv3x3 + bias + PReLU -> NCHW only ----------------
__global__ void __launch_bounds__(256) init_conv_kernel(
    const float* __restrict__ x, const float* __restrict__ wgt,
    const float* __restrict__ bias, const float* __restrict__ prelu_a)
{
    __shared__ float sx[3][18][18];
    __shared__ __align__(8) float sw[27*64];
    __shared__ __align__(8) float sb[64];
    int tid = threadIdx.x;
    int n = blockIdx.y;
    int ty0 = (blockIdx.x >> 3) * 16;
    int tx0 = (blockIdx.x & 7) * 16;

    for (int idx = tid; idx < 1728; idx += 256) {
        int oc = idx & 63;
        int r = idx >> 6;
        int ic = r / 9, tap = r % 9;
        sw[idx] = wgt[(oc*3 + ic)*9 + tap];
    }
    if (tid < 64) sb[tid] = bias[tid];

    const float* xin = x + n*3*HW;
    for (int idx = tid; idx < 3*18*18; idx += 256) {
        int c = idx / 324;
        int r = (idx / 18) % 18;
        int col = idx % 18;
        int gy = ty0 + r - 1, gx = tx0 + col - 1;
        float v = 0.f;
        if (gy >= 0 && gy < H && gx >= 0 && gx < W) v = xin[c*HW + gy*W + gx];
        sx[c][r][col] = v;
    }
    __syncthreads();

    int ly = tid >> 4, lx = tid & 15;
    ull acc2[32];
    #pragma unroll
    for (int o2 = 0; o2 < 32; o2++) acc2[o2] = *(const ull*)&sb[2*o2];

    for (int ic = 0; ic < 3; ic++) {
        #pragma unroll
        for (int tap = 0; tap < 9; tap++) {
            int dy = tap / 3, dx = tap % 3;
            float v = sx[ic][ly + dy][lx + dx];
            ull v2 = pk2(v, v);
            const ull* wp = (const ull*)&sw[(ic*9 + tap)*64];
            #pragma unroll
            for (int o2 = 0; o2 < 32; o2++) ffma2(acc2[o2], v2, wp[o2]);
        }
    }
    float a = prelu_a[0];
    int pix = (ty0 + ly)*W + (tx0 + lx);
    float* dst = g_feats + (size_t)n*NF*HW + pix;
    #pragma unroll
    for (int o2 = 0; o2 < 32; o2++) {
        float2 f = upk2(acc2[o2]);
        dst[(2*o2)*HW]   = (f.x > 0.f) ? f.x : a*f.x;
        dst[(2*o2+1)*HW] = (f.y > 0.f) ? f.y : a*f.y;
    }
}

// ---------------- transpose NCHW -> NHWC ----------------
__global__ void __launch_bounds__(256) transpose_kernel()
{
    __shared__ float tile[64][65];
    int tid = threadIdx.x;
    int n = blockIdx.y;
    int px0 = blockIdx.x * 64;
    const float* src = g_feats + (size_t)n*NF*HW + px0;
    float* dst = g_fnhwc + ((size_t)n*HW + px0)*64;

    #pragma unroll
    for (int i = 0; i < 16; i++) {
        int idx = tid + i*256;
        int c = idx >> 6, xx = idx & 63;
        tile[c][xx] = src[c*HW + xx];
    }
    __syncthreads();
    #pragma unroll
    for (int i = 0; i < 16; i++) {
        int idx = tid + i*256;
        int p = idx >> 6, c = idx & 63;
        dst[p*64 + c] = tile[c][p];
    }
}

// ---------------- kernel B v6: half offset-conv, 8 px/thread, LDS.128 weights ----------------
// 128 threads: q = tid>>5 (oc quarter, warp-uniform); lane: ly=lane>>2 (row), lx=lane&3 (8-px group)
// tile 8 rows x 32 cols; cp.async double-buffered; weights prestaged via g_hw
__global__ void __launch_bounds__(128, 4) half_conv_kernel()
{
    __shared__ __align__(16) float st[2][8][10][44];   // [buf][c][row][col]; interior cols 4..35, halo 3/36
    __shared__ __align__(16) float ws[2][2304];        // [buf][(c*9+tap)*32 + slot]
    int tid = threadIdx.x;
    int task = blockIdx.y;
    int b = task / 6, s = task % 6;
    int tsel = (s == 0) ? 0 : (s - 1);
    int icg  = (s == 0) ? 0 : 1;
    int y0 = (blockIdx.x >> 2) * 8;
    int x0 = (blockIdx.x & 3) * 32;

    const float* src  = g_feats + (size_t)((b*TT + tsel)*NF)*HW;
    const float* wsrc = g_hw + icg*64*9*32;

    int q    = tid >> 5;
    int lane = tid & 31;
    int ly   = lane >> 2;
    int lx   = lane & 3;

    uint32_t st_sm = (uint32_t)__cvta_generic_to_shared(&st[0][0][0][0]);
    uint32_t ws_sm = (uint32_t)__cvta_generic_to_shared(&ws[0][0]);
    const uint32_t ST_BUF = 8*10*44*4;
    const uint32_t WS_BUF = 2304*4;

    auto stage = [&](int icb, int buf) {
        uint32_t stb = st_sm + buf*ST_BUF;
        // interior: 8c x 10rows x 8 segs of 4 floats
        for (int idx = tid; idx < 640; idx += 128) {
            int c = idx / 80;
            int rem = idx % 80;
            int rr = rem >> 3, seg = rem & 7;
            int gy = y0 + rr - 1;
            bool p = (gy >= 0) && (gy < H);
            const float* g = src + (icb + c)*HW + (p ? gy : 0)*W + x0 + seg*4;
            cp_async16(stb + (((c*10 + rr)*44) + 4 + seg*4)*4, g, p);
        }
        // halo: 8c x 10rows x 2 sides
        for (int idx = tid; idx < 160; idx += 128) {
            int c = idx / 20;
            int rem = idx % 20;
            int rr = rem >> 1, side = rem & 1;
            int gy = y0 + rr - 1;
            int gx = side ? (x0 + 32) : (x0 - 1);
            bool p = (gy >= 0) && (gy < H) && (gx >= 0) && (gx < W);
            int col = side ? 36 : 3;
            cp_async4(stb + (((c*10 + rr)*44) + col)*4, src + (icb + c)*HW + (p ? gy*W + gx : 0), p);
        }
        // weights: contiguous 2304 floats = 576 x 16B
        uint32_t wsb = ws_sm + buf*WS_BUF;
        const float* base = wsrc + icb*9*32;
        for (int idx = tid; idx < 576; idx += 128) {
            cp_async16(wsb + idx*16, base + idx*4, true);
        }
    };

    ull acc2[4][8];
    #pragma unroll
    for (int o2 = 0; o2 < 4; o2++)
        #pragma unroll
        for (int p = 0; p < 8; p++) acc2[o2][p] = 0ULL;

    stage(0, 0);
    asm volatile("cp.async.commit_group;");

    for (int ci = 0; ci < 8; ci++) {
        int buf = ci & 1;
        if (ci < 7) {
            stage((ci + 1)*8, buf ^ 1);
            asm volatile("cp.async.commit_group;");
            asm volatile("cp.async.wait_group 1;");
        } else {
            asm volatile("cp.async.wait_group 0;");
        }
        __syncthreads();

        const float (*stb)[10][44] = st[buf];
        const float* wsb = ws[buf];
        int cb = 4 + 8*lx;

        #pragma unroll
        for (int c = 0; c < 8; c++) {
            #pragma unroll
            for (int dy = 0; dy < 3; dy++) {
                const float* rp = &stb[c][ly + dy][0];
                float4 a  = *(const float4*)(rp + cb);
                float4 bb = *(const float4*)(rp + cb + 4);
                float hl = rp[cb - 1], hr = rp[cb + 8];
                ull iv[10];
                iv[0] = pk2(hl, hl);
                iv[1] = pk2(a.x, a.x);  iv[2] = pk2(a.y, a.y);
                iv[3] = pk2(a.z, a.z);  iv[4] = pk2(a.w, a.w);
                iv[5] = pk2(bb.x, bb.x); iv[6] = pk2(bb.y, bb.y);
                iv[7] = pk2(bb.z, bb.z); iv[8] = pk2(bb.w, bb.w);
                iv[9] = pk2(hr, hr);
                #pragma unroll
                for (int dx = 0; dx < 3; dx++) {
                    const ulonglong2* wp = (const ulonglong2*)&wsb[(c*9 + dy*3 + dx)*32 + q*8];
                    ulonglong2 wA = wp[0];
                    ulonglong2 wB = wp[1];
                    #pragma unroll
                    for (int p = 0; p < 8; p++) {
                        ull v = iv[p + dx];
                        ffma2(acc2[0][p], v, wA.x);
                        ffma2(acc2[1][p], v, wA.y);
                        ffma2(acc2[2][p], v, wB.x);
                        ffma2(acc2[3][p], v, wB.y);
                    }
                }
            }
        }
        __syncthreads();   // release buf for stage at ci+2
    }

    // epilogue: 7 real oc per quarter, 8 px -> 2x STG.128 each
    float* dst = g_half + (size_t)(task*27)*HW + (y0 + ly)*W + x0 + 8*lx;
    #pragma unroll
    for (int i = 0; i < 7; i++) {
        int oc = q*7 + i;
        if (oc >= 27) break;
        float4 lo, hi;
        float* lv = (float*)&lo;
        float* hv = (float*)&hi;
        #pragma unroll
        for (int p = 0; p < 4; p++) {
            float2 f = upk2(acc2[i >> 1][p]);
            lv[p] = (i & 1) ? f.y : f.x;
        }
        #pragma unroll
        for (int p = 4; p < 8; p++) {
            float2 f = upk2(acc2[i >> 1][p]);
            hv[p - 4] = (i & 1) ? f.y : f.x;
        }
        *(float4*)(dst + (size_t)oc*HW) = lo;
        *(float4*)(dst + (size_t)oc*HW + 4) = hi;
    }
}

// ---------------- kernel C: dcn (unchanged), 4 blocks/SM ----------------
__global__ void __launch_bounds__(128, 4) dcn_kernel(
    const float* __restrict__ offm_b, const float* __restrict__ dcn_b,
    float* __restrict__ out)
{
    extern __shared__ __align__(16) float smem[];
    float* S   = smem;                                 // [c][128], 8-px blocks xor-swizzled
    float* Wt  = smem + 64*128;                        // [c][o]
    int*   sAi = (int*)(smem + 64*128 + 64*64);        // [4][128]
    float* sWm = (float*)(sAi + 4*128);                // [4][128]

    int tid = threadIdx.x;
    int jb = blockIdx.y;
    int j = jb >> 1, b = jb & 1;
    int y = blockIdx.x;

    const float* fb = g_fnhwc + (size_t)(b*TT + j)*HW*64;
    const float* h0 = g_half + (size_t)((b*6 + 0)*27)*HW;
    const float* h1 = g_half + (size_t)((b*6 + 1 + j)*27)*HW;

    int tx = tid & 15;
    int ty = tid >> 4;

    ull acc2[8][4];
    #pragma unroll
    for (int o = 0; o < 8; o++)
        #pragma unroll
        for (int p = 0; p < 4; p++) acc2[o][p] = 0ULL;

    for (int k = 0; k < 9; k++) {
        __syncthreads();

        #pragma unroll
        for (int i = 0; i < 32; i++) Wt[tid + i*128] = g_wt[k*4096 + tid + i*128];

        {
            int gx = tid;
            int pix = y*W + gx;
            float oy = h0[k*HW + pix] + h1[k*HW + pix] + offm_b[k];
            float ox = h0[(9+k)*HW + pix] + h1[(9+k)*HW + pix] + offm_b[9+k];
            float mm = h0[(18+k)*HW + pix] + h1[(18+k)*HW + pix] + offm_b[18+k];
            float mask = 1.f / (1.f + expf(-mm));
            float py  = (float)(y + (k/3) - 1) + oy;
            float pxf = (float)(gx + (k%3) - 1) + ox;
            float y0f = floorf(py), x0f = floorf(pxf);
            float lyf = py - y0f, lxf = pxf - x0f;
            int yi = (int)y0f, xi = (int)x0f;
            bool vy0 = (yi >= 0) & (yi < H);
            bool vy1 = (yi >= -1) & (yi < H-1);
            bool vx0 = (xi >= 0) & (xi < W);
            bool vx1 = (xi >= -1) & (xi < W-1);
            int yc0 = min(max(yi, 0), H-1);
            int yc1 = min(max(yi+1, 0), H-1);
            int xc0 = min(max(xi, 0), W-1);
            int xc1 = min(max(xi+1, 0), W-1);
            float wy0 = 1.f - lyf, wy1 = lyf, wx0 = 1.f - lxf, wx1 = lxf;
            sAi[0*128 + tid] = (yc0*W + xc0) * 64;  sWm[0*128 + tid] = (vy0 && vx0) ? wy0*wx0*mask : 0.f;
            sAi[1*128 + tid] = (yc0*W + xc1) * 64;  sWm[1*128 + tid] = (vy0 && vx1) ? wy0*wx1*mask : 0.f;
            sAi[2*128 + tid] = (yc1*W + xc0) * 64;  sWm[2*128 + tid] = (vy1 && vx0) ? wy1*wx0*mask : 0.f;
            sAi[3*128 + tid] = (yc1*W + xc1) * 64;  sWm[3*128 + tid] = (vy1 && vx1) ? wy1*wx1*mask : 0.f;
        }
        __syncthreads();

        #pragma unroll
        for (int it = 0; it < 8; it++) {
            int task = tid + it*128;
            int px = task >> 3;
            int qq = task & 7;
            int a0 = sAi[0*128 + px], a1 = sAi[1*128 + px];
            int a2 = sAi[2*128 + px], a3 = sAi[3*128 + px];
            float w0 = sWm[0*128 + px], w1 = sWm[1*128 + px];
            float w2 = sWm[2*128 + px], w3 = sWm[3*128 + px];
            int blk = px >> 3, pof = px & 7;
            #pragma unroll
            for (int i = 0; i < 2; i++) {
                int ch4 = qq + i*8;
                float4 v0 = *(const float4*)(fb + a0 + ch4*4);
                float4 v1 = *(const float4*)(fb + a1 + ch4*4);
                float4 v2 = *(const float4*)(fb + a2 + ch4*4);
                float4 v3 = *(const float4*)(fb + a3 + ch4*4);
                float4 r;
                r.x = fmaf(w3, v3.x, fmaf(w2, v2.x, fmaf(w1, v1.x, w0*v0.x)));
                r.y = fmaf(w3, v3.y, fmaf(w2, v2.y, fmaf(w1, v1.y, w0*v0.y)));
                r.z = fmaf(w3, v3.z, fmaf(w2, v2.z, fmaf(w1, v1.z, w0*v0.z)));
                r.w = fmaf(w3, v3.w, fmaf(w2, v2.w, fmaf(w1, v1.w, w0*v0.w)));
                int xb = ((blk ^ (ch4 & 3)) << 3) + pof;
                int c0 = ch4*4;
                S[(c0+0)*128 + xb] = r.x;
                S[(c0+1)*128 + xb] = r.y;
                S[(c0+2)*128 + xb] = r.z;
                S[(c0+3)*128 + xb] = r.w;
            }
        }
        __syncthreads();

        #pragma unroll 4
        for (int kk = 0; kk < 64; kk++) {
            float4 wA0 = *(const float4*)&Wt[kk*64 + ty*8];
            float4 wA1 = *(const float4*)&Wt[kk*64 + ty*8 + 4];
            int xb = (tx ^ ((kk >> 2) & 3)) << 3;
            const ull* bp = (const ull*)&S[kk*128 + xb];
            ull b0 = bp[0], b1 = bp[1], b2 = bp[2], b3 = bp[3];
            ull sv;
            sv = pk2(wA0.x, wA0.x); ffma2(acc2[0][0], sv, b0); ffma2(acc2[0][1], sv, b1); ffma2(acc2[0][2], sv, b2); ffma2(acc2[0][3], sv, b3);
            sv = pk2(wA0.y, wA0.y); ffma2(acc2[1][0], sv, b0); ffma2(acc2[1][1], sv, b1); ffma2(acc2[1][2], sv, b2); ffma2(acc2[1][3], sv, b3);
            sv = pk2(wA0.z, wA0.z); ffma2(acc2[2][0], sv, b0); ffma2(acc2[2][1], sv, b1); ffma2(acc2[2][2], sv, b2); ffma2(acc2[2][3], sv, b3);
            sv = pk2(wA0.w, wA0.w); ffma2(acc2[3][0], sv, b0); ffma2(acc2[3][1], sv, b1); ffma2(acc2[3][2], sv, b2); ffma2(acc2[3][3], sv, b3);
            sv = pk2(wA1.x, wA1.x); ffma2(acc2[4][0], sv, b0); ffma2(acc2[4][1], sv, b1); ffma2(acc2[4][2], sv, b2); ffma2(acc2[4][3], sv, b3);
            sv = pk2(wA1.y, wA1.y); ffma2(acc2[5][0], sv, b0); ffma2(acc2[5][1], sv, b1); ffma2(acc2[5][2], sv, b2); ffma2(acc2[5][3], sv, b3);
            sv = pk2(wA1.z, wA1.z); ffma2(acc2[6][0], sv, b0); ffma2(acc2[6][1], sv, b1); ffma2(acc2[6][2], sv, b2); ffma2(acc2[6][3], sv, b3);
            sv = pk2(wA1.w, wA1.w); ffma2(acc2[7][0], sv, b0); ffma2(acc2[7][1], sv, b1); ffma2(acc2[7][2], sv, b2); ffma2(acc2[7][3], sv, b3);
        }
    }

    float* ob = out + (size_t)jb*64*HW + y*W + tx*8;
    #pragma unroll
    for (int o = 0; o < 8; o++) {
        int oc = ty*8 + o;
        float bi = __ldg(&dcn_b[oc]);
        float2 f0 = upk2(acc2[o][0]);
        float2 f1 = upk2(acc2[o][1]);
        float2 f2 = upk2(acc2[o][2]);
        float2 f3 = upk2(acc2[o][3]);
        float4 lo, hi;
        lo.x = f0.x + bi; lo.y = f0.y + bi; lo.z = f1.x + bi; lo.w = f1.y + bi;
        hi.x = f2.x + bi; hi.y = f2.y + bi; hi.z = f3.x + bi; hi.w = f3.y + bi;
        *(float4*)(ob + (size_t)oc*HW) = lo;
        *(float4*)(ob + (size_t)oc*HW + 4) = hi;
    }
}

// ---------------- launch ----------------
extern "C" void kernel_launch(void* const* d_in, const int* in_sizes, int n_in,
                              void* d_out, int out_size) {
    const float* x       = (const float*)d_in[0];
    const float* init_w  = (const float*)d_in[1];
    const float* init_b  = (const float*)d_in[2];
    const float* prelu_a = (const float*)d_in[3];
    const float* offm_w  = (const float*)d_in[4];
    const float* offm_b  = (const float*)d_in[5];
    const float* dcn_w   = (const float*)d_in[6];
    const float* dcn_b   = (const float*)d_in[7];
    float* out = (float*)d_out;

    static bool attr_set = false;
    if (!attr_set) {
        cudaFuncSetAttribute(dcn_kernel, cudaFuncAttributeMaxDynamicSharedMemorySize, 53248);
        attr_set = true;
    }

    wprep_kernel<<<(9*64*64 + 255)/256, 256>>>(dcn_w);
    whprep_kernel<<<(2*64*9*32 + 255)/256, 256>>>(offm_w);
    init_conv_kernel<<<dim3(64, 10), 256>>>(x, init_w, init_b, prelu_a);
    transpose_kernel<<<dim3(256, 10), 256>>>();
    half_conv_kernel<<<dim3(64, 12), 128>>>();
    dcn_kernel<<<dim3(128, 10), 128, 53248>>>(offm_b, dcn_b, out);
}